// round 11
// baseline (speedup 1.0000x reference)
#include <cuda_runtime.h>

// GRNN scan: B=512, T=8192, state dim 2.
//
// ONE kernel, 16 CTAs x 128 threads, 32 batches per CTA (1 per lane).
// Four specialized warps per CTA, barrier-staged pipeline (stage = 32 steps),
// double-buffered smem by stage parity:
//   warp 3 (riccati): lane0 runs the batch-independent symmetric Riccati with
//           (u,v) packed in f32x2 (FFMA2): 9 fma-pipe slots/step.
//   warp 2 (prep):    loads dy coalesced along t, computes w_t = X_t dy and
//           G_t = dt(A - X_t C) into smem.
//   warp 0 (scan):    serial chain, pure smem, lookahead-4 pipeline:
//           store x (pre-update); x += clamp(G x + w, +-0.1).
//           (6 fma-pipe slots; FMNMX clamps ride the alu pipe for free.)
//   warp 1 (drain):   out_t = dt C x_t from smem tile -> gmem, coalesced.
// Runtime specialization for C == I, D diagonal (true for this dataset);
// fully general fallback kept.

#define T_STEPS 8192
#define NBATCH  512
#define DTF     1e-3f
#define CLIPX   0.1f
#define STG     32
#define NSTG    (T_STEPS / STG)
#define LA      4

typedef unsigned long long ull;

struct Smem {
    ull    Xuv[2][STG];        // riccati -> prep: packed (x00, x11)
    float  Xr[2][STG];         // riccati -> prep: x01 (== x10 in special path)
    float  Xr2[2][STG];        // general path only: x10
    float4 G[2][STG];          // prep -> scan (broadcast reads)
    float2 w[2][STG][33];      // prep -> scan, [t][b], padded
    float2 o[2][STG][33];      // scan -> drain, [t][b], padded
};

__device__ __forceinline__ float clamp1(float v, float lo, float hi) {
    return fminf(fmaxf(v, lo), hi);
}
__device__ __forceinline__ ull fpack(float lo, float hi) {
    ull d; asm("mov.b64 %0, {%1, %2};" : "=l"(d) : "f"(lo), "f"(hi)); return d;
}
__device__ __forceinline__ void funpack(float& lo, float& hi, ull v) {
    asm("mov.b64 {%0, %1}, %2;" : "=f"(lo), "=f"(hi) : "l"(v));
}
__device__ __forceinline__ ull fma2(ull a, ull b, ull c) {
    ull d; asm("fma.rn.f32x2 %0, %1, %2, %3;" : "=l"(d) : "l"(a), "l"(b), "l"(c));
    return d;
}
__device__ __forceinline__ ull mul2(ull a, ull b) {
    ull d; asm("mul.rn.f32x2 %0, %1, %2;" : "=l"(d) : "l"(a), "l"(b)); return d;
}

// ---------------------------------------------------------------------------
template <bool SPECIAL>
__device__ void cta_run(const float2* __restrict__ dy,
                        const float* __restrict__ A,
                        const float* __restrict__ C,
                        const float* __restrict__ D,
                        float2* __restrict__ outg,
                        Smem* sm, int wid, int lane, int b0) {
    const float a00 = A[0], a01 = A[1], a10 = A[2], a11 = A[3];
    const float c00 = C[0], c01 = C[1], c10 = C[2], c11 = C[3];
    const float d00 = D[0], d01 = D[1], d10 = D[2], d11 = D[3];

    const float dta00 = DTF * a00, dta01 = DTF * a01;
    const float dta10 = DTF * a10, dta11 = DTF * a11;
    const float dtc00 = DTF * c00, dtc01 = DTF * c01;
    const float dtc10 = DTF * c10, dtc11 = DTF * c11;

    // ---- riccati constants (SPECIAL: u=p00+d0, r=p01, v=p11+d1;
    //      X=[[u,r],[r,v]]; clip([-1,1]) provably inactive: monotone decay) ----
    const float KU1 = 1.0f + 2.0f * DTF * a00;
    const float KU2 = 2.0f * DTF * a01;
    const float KU3 = DTF * d00 * (1.0f - 2.0f * a00);
    const float KV1 = 1.0f + 2.0f * DTF * a11;
    const float KV2 = 2.0f * DTF * a10;
    const float KV3 = DTF * d11 * (1.0f - 2.0f * a11);
    const float KR1 = DTF * a10;
    const float KR2 = DTF * a01;
    const float KR3 = 1.0f + DTF * (a00 + a11);
    const float KR4 = -DTF * fmaf(a10, d00, a01 * d11);
    // packed constants for the f32x2 path
    const ull K1p    = fpack(KU1, KV1);
    const ull K23p   = fpack(KU3, KV3);           // additive consts
    const ull K2p    = fpack(KU2, KV2);
    const ull KR12p  = fpack(KR1, KR2);
    const ull negdtp = fpack(-DTF, -DTF);
    // general-path constants (q-form)
    const float k00a = 1.0f + 2.0f * DTF * a00, k00b = 2.0f * DTF * a01;
    const float k00c = DTF * d00;
    const float k01a = DTF * a10, k01b = 1.0f + DTF * (a00 + a11);
    const float k01d = DTF * a01, k01c = DTF * d01;
    const float k11a = 1.0f + 2.0f * DTF * a11, k11b = 2.0f * DTF * a10;
    const float k11c = DTF * d11;

    // persistent per-warp state
    ull   uvp = fpack(1.0f + d00, 1.0f + d11);    // riccati SPECIAL (u,v)
    float rsc = 0.0f;                             // riccati SPECIAL r
    float p00 = 1.0f, p01 = 0.0f, p11 = 1.0f;     // riccati general
    float x0 = 1.0f, x1 = 0.0f;                   // scan state [1,0]

    for (int k = 0; k < NSTG + 3; ++k) {
        __syncthreads();

        if (wid == 3) {                     // ---------------- riccati: stage k
            if (k < NSTG && lane == 0) {
                const int slot = k & 1;
                if (SPECIAL) {
#pragma unroll 8
                    for (int i = 0; i < STG; ++i) {
                        sm->Xuv[slot][i] = uvp;                 // STS.64
                        sm->Xr[slot][i]  = rsc;                 // STS.32
                        // fma-pipe: 6 packed + 3 scalar = 9 slots.
                        const ull rp   = fpack(rsc, rsc);       // alu
                        const ull r2p  = mul2(rp, rp);
                        const ull sp   = fma2(negdtp, uvp, K1p);
                        const ull accp = fma2(K2p, rp, K23p);
                        const ull t12  = fma2(negdtp, rp, KR12p);
                        const ull inn  = fma2(sp, uvp, accp);
                        const ull nuv  = fma2(negdtp, r2p, inn);
                        float u, v, t1, t2;
                        funpack(u, v, uvp);                     // alu
                        funpack(t1, t2, t12);                   // alu
                        rsc = fmaf(t1, u, fmaf(t2, v, fmaf(KR3, rsc, KR4)));
                        uvp = nuv;
                    }
                } else {
#pragma unroll 2
                    for (int i = 0; i < STG; ++i) {
                        float x00 = fmaf(p00, c00, fmaf(p01, c01, d00));
                        float x01 = fmaf(p00, c10, fmaf(p01, c11, d10));
                        float x10 = fmaf(p01, c00, fmaf(p11, c01, d01));
                        float x11 = fmaf(p01, c10, fmaf(p11, c11, d11));
                        sm->Xuv[slot][i] = fpack(x00, x11);
                        sm->Xr[slot][i]  = x01;
                        sm->Xr2[slot][i] = x10;
                        float q00 = fmaf(k00a, p00, fmaf(k00b, p01, k00c));
                        float q01 = fmaf(k01a, p00, fmaf(k01b, p01, fmaf(k01d, p11, k01c)));
                        float q11 = fmaf(k11a, p11, fmaf(k11b, p01, k11c));
                        float m00 = fmaf(x00, x00, x01 * x01);
                        float m01 = fmaf(x00, x10, x01 * x11);
                        float m11 = fmaf(x10, x10, x11 * x11);
                        p00 = clamp1(fmaf(-DTF, m00, q00), -1.0f, 1.0f);
                        p01 = clamp1(fmaf(-DTF, m01, q01), -1.0f, 1.0f);
                        p11 = clamp1(fmaf(-DTF, m11, q11), -1.0f, 1.0f);
                    }
                }
            }
        } else if (wid == 2) {              // ---------------- prep: stage k-1
            const int s = k - 1;
            if (s >= 0 && s < NSTG) {
                const int slot = s & 1;
                float u, v;
                funpack(u, v, sm->Xuv[slot][lane]);   // my t = s*STG + lane
                const float r01 = sm->Xr[slot][lane];
                const float r10 = SPECIAL ? r01 : sm->Xr2[slot][lane];
                float4 Gv;
                if (SPECIAL) {
                    Gv = make_float4(fmaf(-DTF, u,   dta00),
                                     fmaf(-DTF, r01, dta01),
                                     fmaf(-DTF, r01, dta10),
                                     fmaf(-DTF, v,   dta11));
                } else {
                    Gv = make_float4(
                        fmaf(-u,   dtc00, fmaf(-r01, dtc10, dta00)),
                        fmaf(-u,   dtc01, fmaf(-r01, dtc11, dta01)),
                        fmaf(-r10, dtc00, fmaf(-v,   dtc10, dta10)),
                        fmaf(-r10, dtc01, fmaf(-v,   dtc11, dta11)));
                }
                sm->G[slot][lane] = Gv;

                const size_t tb = (size_t)s * STG + lane;
                float2 dbuf[16];
#pragma unroll
                for (int h = 0; h < 2; ++h) {
#pragma unroll
                    for (int j = 0; j < 16; ++j)
                        dbuf[j] = __ldg(&dy[(size_t)(b0 + h * 16 + j) * T_STEPS + tb]);
#pragma unroll
                    for (int j = 0; j < 16; ++j) {
                        sm->w[slot][lane][h * 16 + j] =
                            make_float2(fmaf(u,   dbuf[j].x, r01 * dbuf[j].y),
                                        fmaf(r10, dbuf[j].x, v   * dbuf[j].y));
                    }
                }
            }
        } else if (wid == 0) {              // ---------------- scan: stage k-2
            const int s = k - 2;
            if (s >= 0 && s < NSTG) {
                const int slot = s & 1;
                float2 wr[LA]; float4 Gr[LA];
#pragma unroll
                for (int j = 0; j < LA; ++j) {
                    wr[j] = sm->w[slot][j][lane];
                    Gr[j] = sm->G[slot][j];
                }
#pragma unroll
                for (int i = 0; i < STG; ++i) {
                    const float2 wc = wr[i % LA];
                    const float4 Gc = Gr[i % LA];
                    if (i + LA < STG) {
                        wr[i % LA] = sm->w[slot][i + LA][lane];
                        Gr[i % LA] = sm->G[slot][i + LA];
                    }
                    sm->o[slot][i][lane] = make_float2(x0, x1);  // pre-update x
                    const float dx0 = fmaf(Gc.x, x0, fmaf(Gc.y, x1, wc.x));
                    const float dx1 = fmaf(Gc.z, x0, fmaf(Gc.w, x1, wc.y));
                    x0 += clamp1(dx0, -CLIPX, CLIPX);
                    x1 += clamp1(dx1, -CLIPX, CLIPX);
                }
            }
        } else {                            // ---------------- drain: stage k-3
            const int s = k - 3;
            if (s >= 0 && s < NSTG) {
                const int slot = s & 1;
                const int t0 = s * STG;
#pragma unroll 4
                for (int r = 0; r < 32; ++r) {
                    const float2 xv = sm->o[slot][lane][r];
                    float2 vv;
                    if (SPECIAL) {
                        vv = make_float2(DTF * xv.x, DTF * xv.y);
                    } else {
                        vv = make_float2(fmaf(dtc00, xv.x, dtc01 * xv.y),
                                         fmaf(dtc10, xv.x, dtc11 * xv.y));
                    }
                    outg[(size_t)(b0 + r) * T_STEPS + t0 + lane] = vv;
                }
            }
        }
    }
}

// ---------------------------------------------------------------------------
__global__ void __launch_bounds__(128, 1)
fused_kernel(const float* __restrict__ inputs,
             const float* __restrict__ A,
             const float* __restrict__ C,
             const float* __restrict__ D,
             float* __restrict__ out) {
    __shared__ Smem sm;
    const int wid  = threadIdx.x >> 5;
    const int lane = threadIdx.x & 31;
    const int b0   = blockIdx.x * 32;

    const bool special =
        (C[0] == 1.0f && C[1] == 0.0f && C[2] == 0.0f && C[3] == 1.0f &&
         D[1] == 0.0f && D[2] == 0.0f);

    const float2* dy = (const float2*)inputs;
    float2* o = (float2*)out;

    if (special) cta_run<true >(dy, A, C, D, o, &sm, wid, lane, b0);
    else         cta_run<false>(dy, A, C, D, o, &sm, wid, lane, b0);
}

// ---------------------------------------------------------------------------
extern "C" void kernel_launch(void* const* d_in, const int* in_sizes, int n_in,
                              void* d_out, int out_size) {
    const float* inputs = (const float*)d_in[0];   // [512, 8192, 2]
    const float* A      = (const float*)d_in[1];
    const float* C      = (const float*)d_in[2];
    const float* D      = (const float*)d_in[3];
    float*       out    = (float*)d_out;           // [512, 8192, 2]

    fused_kernel<<<NBATCH / 32, 128>>>(inputs, A, C, D, out);
}